// round 7
// baseline (speedup 1.0000x reference)
#include <cuda_runtime.h>
#include <cuda_bf16.h>
#include <cstdint>
#include <math.h>

#define BATCH 4
#define SEQ 4096
#define DIM 512
#define QK 128
#define LN_EPS 1e-5f
#define NJT 32

// bf16 hi/lo split scratch (allocation-free rule: __device__ globals)
__device__ __nv_bfloat16 g_qh[BATCH * SEQ * QK];
__device__ __nv_bfloat16 g_ql[BATCH * SEQ * QK];
__device__ __nv_bfloat16 g_kh[BATCH * SEQ * QK];
__device__ __nv_bfloat16 g_kl[BATCH * SEQ * QK];

// ---------------------------------------------------------------------------
// common helpers
// ---------------------------------------------------------------------------
__device__ __forceinline__ uint32_t smem_u32(const void* p) {
    uint32_t a;
    asm("{ .reg .u64 t; cvta.to.shared.u64 t, %1; cvt.u32.u64 %0, t; }" : "=r"(a) : "l"(p));
    return a;
}
__device__ __forceinline__ void cpasync16(uint32_t dst, const void* src) {
    asm volatile("cp.async.cg.shared.global [%0], [%1], 16;"
                 :: "r"(dst), "l"(__cvta_generic_to_global(src)));
}
__device__ __forceinline__ void ldsm4(uint32_t a, uint32_t& r0, uint32_t& r1,
                                      uint32_t& r2, uint32_t& r3) {
    asm volatile("ldmatrix.sync.aligned.m8n8.x4.shared.b16 {%0,%1,%2,%3}, [%4];"
                 : "=r"(r0), "=r"(r1), "=r"(r2), "=r"(r3) : "r"(a));
}
__device__ __forceinline__ void mma16816(float* c,
                                         const uint32_t* a, uint32_t b0, uint32_t b1) {
    asm volatile("mma.sync.aligned.m16n8k16.row.col.f32.bf16.bf16.f32 "
                 "{%0,%1,%2,%3}, {%4,%5,%6,%7}, {%8,%9}, {%0,%1,%2,%3};"
                 : "+f"(c[0]), "+f"(c[1]), "+f"(c[2]), "+f"(c[3])
                 : "r"(a[0]), "r"(a[1]), "r"(a[2]), "r"(a[3]), "r"(b0), "r"(b1));
}
// swizzled offset: row stride 256B (128 bf16), 16 chunks of 16B, chunk ^= row&7
__device__ __forceinline__ uint32_t swoff(int r, int ch) {
    return (uint32_t)r * 256u + (uint32_t)((ch ^ (r & 7)) << 4);
}

// ---------------------------------------------------------------------------
// Kernel 1 (tensorized, 2 CTAs/SM): LayerNorm + Linear + SiLU + OffsetScale.
// 256 CTAs x (64 rows, 128 out). K=512 in 4 chunks of 128.
// smem: A hi/lo 2x16KB + B hi/lo 2x32KB + stats = ~97KB -> 2 CTAs/SM.
// ---------------------------------------------------------------------------
#define QSA_HI 0
#define QSA_LO 16384
#define QSB_HI 32768
#define QSB_LO 65536
#define QST    98304
#define QK_SMEM (98304 + 1024)

__global__ __launch_bounds__(256, 2) void qk_kernel(
    const float* __restrict__ x,
    const float* __restrict__ lnw, const float* __restrict__ lnb,
    const float* __restrict__ w,   const float* __restrict__ bq,
    const float* __restrict__ gamma, const float* __restrict__ beta)
{
    extern __shared__ char sm[];
    const uint32_t sb = smem_u32(sm);
    float* s_mu = (float*)(sm + QST);
    float* s_rs = s_mu + 64;

    const int tid = threadIdx.x, wid = tid >> 5, lane = tid & 31;
    const int row0 = blockIdx.x * 64;

    // --- LN stats: each warp 8 rows ---
#pragma unroll 1
    for (int rr = 0; rr < 8; ++rr) {
        int r = wid * 8 + rr;
        const float4* xr = (const float4*)(x + (size_t)(row0 + r) * DIM);
        float s = 0.f, sq = 0.f;
#pragma unroll
        for (int i = 0; i < 4; ++i) {
            float4 v = xr[lane + 32 * i];
            s  += v.x + v.y + v.z + v.w;
            sq += v.x * v.x + v.y * v.y + v.z * v.z + v.w * v.w;
        }
#pragma unroll
        for (int o = 16; o > 0; o >>= 1) {
            s  += __shfl_xor_sync(0xFFFFFFFFu, s,  o);
            sq += __shfl_xor_sync(0xFFFFFFFFu, sq, o);
        }
        if (lane == 0) {
            float mu  = s * (1.f / DIM);
            float var = sq * (1.f / DIM) - mu * mu;
            s_mu[r] = mu;
            s_rs[r] = rsqrtf(var + LN_EPS);
        }
    }
    __syncthreads();

    // warp tiling: 2(m) x 4(n); warp tile 32m x 32n
    const int wm0 = (wid & 1) * 32;
    const int wn0 = (wid >> 1) * 32;
    const int a_r  = wm0 + (lane & 15);
    const int a_cb = lane >> 4;
    const int b_n  = wn0 + (lane & 7) + ((lane & 16) >> 1);
    const int b_cb = (lane >> 3) & 1;

    float acc[2][4][4];
#pragma unroll
    for (int mt = 0; mt < 2; ++mt)
#pragma unroll
        for (int n8 = 0; n8 < 4; ++n8)
#pragma unroll
            for (int v = 0; v < 4; ++v) acc[mt][n8][v] = 0.f;

    for (int c = 0; c < 4; ++c) {
        // --- stage A (normalized x, 64 rows): 4 iters x 256 thr ---
#pragma unroll
        for (int i = 0; i < 4; ++i) {
            int idx = tid + 256 * i;
            int r = idx >> 4, ch = idx & 15;
            float mu = s_mu[r], rs = s_rs[r];
            const float* xp = x + (size_t)(row0 + r) * DIM + c * 128 + ch * 8;
            const float* wl = lnw + c * 128 + ch * 8;
            const float* bl = lnb + c * 128 + ch * 8;
            __nv_bfloat16 h8[8], l8[8];
#pragma unroll
            for (int j = 0; j < 8; ++j) {
                float v = (xp[j] - mu) * rs * wl[j] + bl[j];
                h8[j] = __float2bfloat16(v);
                l8[j] = __float2bfloat16(v - __bfloat162float(h8[j]));
            }
            *(uint4*)(sm + QSA_HI + swoff(r, ch)) = *(uint4*)h8;
            *(uint4*)(sm + QSA_LO + swoff(r, ch)) = *(uint4*)l8;
        }
        // --- stage B (W chunk, 128 out rows): 8 iters x 256 thr ---
#pragma unroll
        for (int i = 0; i < 8; ++i) {
            int idx = tid + 256 * i;
            int r = idx >> 4, ch = idx & 15;
            const float* wp = w + (size_t)r * DIM + c * 128 + ch * 8;
            __nv_bfloat16 h8[8], l8[8];
#pragma unroll
            for (int j = 0; j < 8; ++j) {
                float v = wp[j];
                h8[j] = __float2bfloat16(v);
                l8[j] = __float2bfloat16(v - __bfloat162float(h8[j]));
            }
            *(uint4*)(sm + QSB_HI + swoff(r, ch)) = *(uint4*)h8;
            *(uint4*)(sm + QSB_LO + swoff(r, ch)) = *(uint4*)l8;
        }
        __syncthreads();

#pragma unroll
        for (int ks = 0; ks < 8; ++ks) {
            uint32_t ah[2][4], al[2][4];
#pragma unroll
            for (int mt = 0; mt < 2; ++mt) {
                int r = a_r + mt * 16;
                ldsm4(sb + QSA_HI + swoff(r, ks * 2 + a_cb), ah[mt][0], ah[mt][1], ah[mt][2], ah[mt][3]);
                ldsm4(sb + QSA_LO + swoff(r, ks * 2 + a_cb), al[mt][0], al[mt][1], al[mt][2], al[mt][3]);
            }
            uint32_t bh[2][4], bl[2][4];
#pragma unroll
            for (int nb = 0; nb < 2; ++nb) {
                int n = b_n + nb * 16;
                ldsm4(sb + QSB_HI + swoff(n, ks * 2 + b_cb), bh[nb][0], bh[nb][1], bh[nb][2], bh[nb][3]);
                ldsm4(sb + QSB_LO + swoff(n, ks * 2 + b_cb), bl[nb][0], bl[nb][1], bl[nb][2], bl[nb][3]);
            }
#pragma unroll
            for (int mt = 0; mt < 2; ++mt)
#pragma unroll
                for (int n8 = 0; n8 < 4; ++n8) {
                    const int nb = n8 >> 1, hf = (n8 & 1) * 2;
                    mma16816(acc[mt][n8], ah[mt], bh[nb][hf], bh[nb][hf + 1]);
                    mma16816(acc[mt][n8], ah[mt], bl[nb][hf], bl[nb][hf + 1]);
                    mma16816(acc[mt][n8], al[mt], bh[nb][hf], bh[nb][hf + 1]);
                }
        }
        __syncthreads();
    }

    // --- epilogue: bias + SiLU + OffsetScale -> bf16 hi/lo stores ---
#pragma unroll
    for (int n8 = 0; n8 < 4; ++n8) {
        int e0 = wn0 + n8 * 8 + (lane & 3) * 2;
        float bb0 = bq[e0],            bb1 = bq[e0 + 1];
        float g00 = gamma[e0],         g01 = gamma[e0 + 1];
        float b00 = beta[e0],          b01 = beta[e0 + 1];
        float g10 = gamma[QK + e0],    g11 = gamma[QK + e0 + 1];
        float b10 = beta[QK + e0],     b11 = beta[QK + e0 + 1];
#pragma unroll
        for (int mt = 0; mt < 2; ++mt) {
#pragma unroll
            for (int half = 0; half < 2; ++half) {
                int row = row0 + wm0 + mt * 16 + (lane >> 2) + half * 8;
                float z0 = acc[mt][n8][half * 2]     + bb0;
                float z1 = acc[mt][n8][half * 2 + 1] + bb1;
                float v0 = z0 / (1.f + expf(-z0));
                float v1 = z1 / (1.f + expf(-z1));
                float q0 = v0 * g00 + b00, q1 = v1 * g01 + b01;
                float k0 = v0 * g10 + b10, k1 = v1 * g11 + b11;
                __nv_bfloat16 t0, t1;
                size_t off = (size_t)row * QK + e0;
                t0 = __float2bfloat16(q0); t1 = __float2bfloat16(q1);
                *(uint32_t*)(g_qh + off) = (uint32_t)__bfloat16_as_ushort(t0) |
                                           ((uint32_t)__bfloat16_as_ushort(t1) << 16);
                __nv_bfloat16 r0 = __float2bfloat16(q0 - __bfloat162float(t0));
                __nv_bfloat16 r1 = __float2bfloat16(q1 - __bfloat162float(t1));
                *(uint32_t*)(g_ql + off) = (uint32_t)__bfloat16_as_ushort(r0) |
                                           ((uint32_t)__bfloat16_as_ushort(r1) << 16);
                t0 = __float2bfloat16(k0); t1 = __float2bfloat16(k1);
                *(uint32_t*)(g_kh + off) = (uint32_t)__bfloat16_as_ushort(t0) |
                                           ((uint32_t)__bfloat16_as_ushort(t1) << 16);
                r0 = __float2bfloat16(k0 - __bfloat162float(t0));
                r1 = __float2bfloat16(k1 - __bfloat162float(t1));
                *(uint32_t*)(g_kl + off) = (uint32_t)__bfloat16_as_ushort(r0) |
                                           ((uint32_t)__bfloat16_as_ushort(r1) << 16);
            }
        }
    }
}

// ---------------------------------------------------------------------------
// Kernel 2: strip-persistent bf16 hi/lo HMMA sim GEMM (unchanged).
// ---------------------------------------------------------------------------
#define SA_HI 0
#define SA_LO 32768
#define SB0   65536
#define ATT_SMEM 196608

__device__ __forceinline__ void load_tile128(uint32_t dst, const __nv_bfloat16* g, int tid) {
#pragma unroll
    for (int i = 0; i < 8; ++i) {
        int idx = tid + 256 * i;
        int r = idx >> 4, ch = idx & 15;
        cpasync16(dst + swoff(r, ch), g + (size_t)r * QK + ch * 8);
    }
}

__global__ __launch_bounds__(256, 1) void attn_kernel(float* __restrict__ out)
{
    extern __shared__ char smem[];
    const uint32_t sb = smem_u32(smem);
    const int tid = threadIdx.x, wid = tid >> 5, lane = tid & 31;
    const int b = blockIdx.y, strip = blockIdx.x;
    const size_t brow = (size_t)b * SEQ + strip * 128;

    const __nv_bfloat16* qh = g_qh + brow * QK;
    const __nv_bfloat16* ql = g_ql + brow * QK;
    const __nv_bfloat16* khb = g_kh + (size_t)b * SEQ * QK;
    const __nv_bfloat16* klb = g_kl + (size_t)b * SEQ * QK;

    load_tile128(sb + SA_HI, qh, tid);
    load_tile128(sb + SA_LO, ql, tid);
    load_tile128(sb + SB0,         khb, tid);
    load_tile128(sb + SB0 + 32768, klb, tid);
    asm volatile("cp.async.commit_group;" ::: "memory");
    load_tile128(sb + SB0 + 65536,         khb + (size_t)128 * QK, tid);
    load_tile128(sb + SB0 + 65536 + 32768, klb + (size_t)128 * QK, tid);
    asm volatile("cp.async.commit_group;" ::: "memory");

    const int wm0 = (wid & 3) * 32;
    const int wn0 = (wid >> 2) * 64;
    const int a_r  = wm0 + (lane & 15);
    const int a_cb = lane >> 4;
    const int b_n  = wn0 + (lane & 7) + ((lane & 16) >> 1);
    const int b_cb = (lane >> 3) & 1;

    for (int jt = 0; jt < NJT; ++jt) {
        const int s = jt & 1;
        asm volatile("cp.async.wait_group 1;" ::: "memory");
        __syncthreads();

        const uint32_t sBh = sb + SB0 + s * 65536;
        const uint32_t sBl = sBh + 32768;

        float acc[2][8][4];
#pragma unroll
        for (int mt = 0; mt < 2; ++mt)
#pragma unroll
            for (int n8 = 0; n8 < 8; ++n8)
#pragma unroll
                for (int v = 0; v < 4; ++v) acc[mt][n8][v] = 0.f;

#pragma unroll
        for (int ks = 0; ks < 8; ++ks) {
            uint32_t ah[2][4], al[2][4];
#pragma unroll
            for (int mt = 0; mt < 2; ++mt) {
                int r = a_r + mt * 16;
                ldsm4(sb + SA_HI + swoff(r, ks * 2 + a_cb), ah[mt][0], ah[mt][1], ah[mt][2], ah[mt][3]);
                ldsm4(sb + SA_LO + swoff(r, ks * 2 + a_cb), al[mt][0], al[mt][1], al[mt][2], al[mt][3]);
            }
            uint32_t bh[4][4], bl[4][4];
#pragma unroll
            for (int nb = 0; nb < 4; ++nb) {
                int n = b_n + nb * 16;
                ldsm4(sBh + swoff(n, ks * 2 + b_cb), bh[nb][0], bh[nb][1], bh[nb][2], bh[nb][3]);
                ldsm4(sBl + swoff(n, ks * 2 + b_cb), bl[nb][0], bl[nb][1], bl[nb][2], bl[nb][3]);
            }
#pragma unroll
            for (int mt = 0; mt < 2; ++mt)
#pragma unroll
                for (int n8 = 0; n8 < 8; ++n8) {
                    const int nb = n8 >> 1, hf = (n8 & 1) * 2;
                    mma16816(acc[mt][n8], ah[mt], bh[nb][hf], bh[nb][hf + 1]);
                    mma16816(acc[mt][n8], ah[mt], bl[nb][hf], bl[nb][hf + 1]);
                    mma16816(acc[mt][n8], al[mt], bh[nb][hf], bh[nb][hf + 1]);
                }
        }
        __syncthreads();

        if (jt + 2 < NJT) {
            load_tile128(sBh, khb + (size_t)(jt + 2) * 128 * QK, tid);
            load_tile128(sBl, klb + (size_t)(jt + 2) * 128 * QK, tid);
        }
        asm volatile("cp.async.commit_group;" ::: "memory");

#pragma unroll
        for (int mt = 0; mt < 2; ++mt) {
#pragma unroll
            for (int n8 = 0; n8 < 8; ++n8) {
                int grow = wm0 + mt * 16 + (lane >> 2);
                int gcol = jt * 128 + wn0 + n8 * 8 + (lane & 3) * 2;
                float* p0 = out + (brow + grow) * SEQ + gcol;
                float* p1 = p0 + (size_t)8 * SEQ;
                float s0, s1;
                float2 v0, v1;
                s0 = fmaxf(acc[mt][n8][0] * 0.015625f, 0.f); v0.x = s0 * s0;
                s1 = fmaxf(acc[mt][n8][1] * 0.015625f, 0.f); v0.y = s1 * s1;
                s0 = fmaxf(acc[mt][n8][2] * 0.015625f, 0.f); v1.x = s0 * s0;
                s1 = fmaxf(acc[mt][n8][3] * 0.015625f, 0.f); v1.y = s1 * s1;
                *(float2*)p0 = v0;
                *(float2*)p1 = v1;
            }
        }
    }
}

// ---------------------------------------------------------------------------
// Kernel 3: per-row sum + in-place rescale.
// ---------------------------------------------------------------------------
__global__ __launch_bounds__(256) void norm_kernel(float* __restrict__ out)
{
    const size_t row = blockIdx.x;
    float4* p = (float4*)(out + row * SEQ);
    const int tid = threadIdx.x;

    float4 v[4];
    float s = 0.f;
#pragma unroll
    for (int i = 0; i < 4; ++i) {
        v[i] = p[tid + 256 * i];
        s += v[i].x + v[i].y + v[i].z + v[i].w;
    }

    __shared__ float red[256];
    red[tid] = s;
    __syncthreads();
#pragma unroll
    for (int o = 128; o > 0; o >>= 1) {
        if (tid < o) red[tid] += red[tid + o];
        __syncthreads();
    }
    float inv = 1.f / (red[0] + 1e-6f);

#pragma unroll
    for (int i = 0; i < 4; ++i) {
        v[i].x *= inv; v[i].y *= inv; v[i].z *= inv; v[i].w *= inv;
        p[tid + 256 * i] = v[i];
    }
}

// ---------------------------------------------------------------------------
extern "C" void kernel_launch(void* const* d_in, const int* in_sizes, int n_in,
                              void* d_out, int out_size)
{
    const float* x     = (const float*)d_in[0];
    const float* ln_w  = (const float*)d_in[1];
    const float* ln_b  = (const float*)d_in[2];
    const float* w_qk  = (const float*)d_in[3];
    const float* b_qk  = (const float*)d_in[4];
    const float* gamma = (const float*)d_in[5];
    const float* beta  = (const float*)d_in[6];
    float* out = (float*)d_out;

    cudaFuncSetAttribute(qk_kernel, cudaFuncAttributeMaxDynamicSharedMemorySize, QK_SMEM);
    qk_kernel<<<(BATCH * SEQ) / 64, 256, QK_SMEM>>>(x, ln_w, ln_b, w_qk, b_qk, gamma, beta);

    cudaFuncSetAttribute(attn_kernel, cudaFuncAttributeMaxDynamicSharedMemorySize, ATT_SMEM);
    dim3 g2(SEQ / 128, BATCH);
    attn_kernel<<<g2, 256, ATT_SMEM>>>(out);

    norm_kernel<<<BATCH * SEQ, 256>>>(out);
}

// round 8
// speedup vs baseline: 1.0023x; 1.0023x over previous
#include <cuda_runtime.h>
#include <cuda_bf16.h>
#include <cstdint>
#include <math.h>

#define BATCH 4
#define SEQ 4096
#define DIM 512
#define QK 128
#define LN_EPS 1e-5f
#define NJT 32

// scratch (allocation-free rule: __device__ globals)
__device__ __nv_bfloat16 g_qh[BATCH * SEQ * QK];
__device__ __nv_bfloat16 g_ql[BATCH * SEQ * QK];
__device__ __nv_bfloat16 g_kh[BATCH * SEQ * QK];
__device__ __nv_bfloat16 g_kl[BATCH * SEQ * QK];
__device__ __nv_bfloat16 g_wh[QK * DIM];
__device__ __nv_bfloat16 g_wl[QK * DIM];

// ---------------------------------------------------------------------------
// common helpers
// ---------------------------------------------------------------------------
__device__ __forceinline__ uint32_t smem_u32(const void* p) {
    uint32_t a;
    asm("{ .reg .u64 t; cvta.to.shared.u64 t, %1; cvt.u32.u64 %0, t; }" : "=r"(a) : "l"(p));
    return a;
}
__device__ __forceinline__ void cpasync16(uint32_t dst, const void* src) {
    asm volatile("cp.async.cg.shared.global [%0], [%1], 16;"
                 :: "r"(dst), "l"(__cvta_generic_to_global(src)));
}
__device__ __forceinline__ void ldsm4(uint32_t a, uint32_t& r0, uint32_t& r1,
                                      uint32_t& r2, uint32_t& r3) {
    asm volatile("ldmatrix.sync.aligned.m8n8.x4.shared.b16 {%0,%1,%2,%3}, [%4];"
                 : "=r"(r0), "=r"(r1), "=r"(r2), "=r"(r3) : "r"(a));
}
__device__ __forceinline__ void mma16816(float* c,
                                         const uint32_t* a, uint32_t b0, uint32_t b1) {
    asm volatile("mma.sync.aligned.m16n8k16.row.col.f32.bf16.bf16.f32 "
                 "{%0,%1,%2,%3}, {%4,%5,%6,%7}, {%8,%9}, {%0,%1,%2,%3};"
                 : "+f"(c[0]), "+f"(c[1]), "+f"(c[2]), "+f"(c[3])
                 : "r"(a[0]), "r"(a[1]), "r"(a[2]), "r"(a[3]), "r"(b0), "r"(b1));
}
// swizzled offset: row stride 256B (128 bf16), 16 chunks of 16B, chunk ^= row&7
__device__ __forceinline__ uint32_t swoff(int r, int ch) {
    return (uint32_t)r * 256u + (uint32_t)((ch ^ (r & 7)) << 4);
}

// ---------------------------------------------------------------------------
// Kernel 0: split W into bf16 hi/lo once (128x512 = 64K elems).
// ---------------------------------------------------------------------------
__global__ __launch_bounds__(256) void wsplit_kernel(const float* __restrict__ w)
{
    int idx = (blockIdx.x * 256 + threadIdx.x) * 8;
    __nv_bfloat16 h8[8], l8[8];
#pragma unroll
    for (int j = 0; j < 8; ++j) {
        float v = w[idx + j];
        h8[j] = __float2bfloat16(v);
        l8[j] = __float2bfloat16(v - __bfloat162float(h8[j]));
    }
    *(uint4*)(g_wh + idx) = *(uint4*)h8;
    *(uint4*)(g_wl + idx) = *(uint4*)l8;
}

// ---------------------------------------------------------------------------
// Kernel 1: LayerNorm + Linear + SiLU + OffsetScale (W via async bf16 tiles).
// 256 CTAs x (64 rows, 128 out). K=512 in 4 chunks, W double-buffered.
// smem: A hi/lo 32KB + W 2 stages x 64KB + stats = ~162KB.
// ---------------------------------------------------------------------------
#define QSA_HI 0
#define QSA_LO 16384
#define QSW0   32768           // stage s at + s*65536; lo at +32768
#define QST    163840
#define QK_SMEM (163840 + 1024)

__global__ __launch_bounds__(256, 1) void qk_kernel(
    const float* __restrict__ x,
    const float* __restrict__ lnw, const float* __restrict__ lnb,
    const float* __restrict__ bq,
    const float* __restrict__ gamma, const float* __restrict__ beta)
{
    extern __shared__ char sm[];
    const uint32_t sb = smem_u32(sm);
    float* s_mu = (float*)(sm + QST);
    float* s_rs = s_mu + 64;

    const int tid = threadIdx.x, wid = tid >> 5, lane = tid & 31;
    const int row0 = blockIdx.x * 64;

    // prologue: W chunks 0 and 1 in flight (pure cp.async of bf16)
#pragma unroll
    for (int s = 0; s < 2; ++s) {
#pragma unroll
        for (int i = 0; i < 8; ++i) {
            int idx = tid + 256 * i;
            int r = idx >> 4, ch = idx & 15;
            cpasync16(sb + QSW0 + s * 65536 + swoff(r, ch),
                      g_wh + (size_t)r * DIM + s * 128 + ch * 8);
            cpasync16(sb + QSW0 + s * 65536 + 32768 + swoff(r, ch),
                      g_wl + (size_t)r * DIM + s * 128 + ch * 8);
        }
        asm volatile("cp.async.commit_group;" ::: "memory");
    }

    // --- LN stats: each warp 8 rows (overlaps W loads) ---
#pragma unroll 1
    for (int rr = 0; rr < 8; ++rr) {
        int r = wid * 8 + rr;
        const float4* xr = (const float4*)(x + (size_t)(row0 + r) * DIM);
        float s = 0.f, sq = 0.f;
#pragma unroll
        for (int i = 0; i < 4; ++i) {
            float4 v = xr[lane + 32 * i];
            s  += v.x + v.y + v.z + v.w;
            sq += v.x * v.x + v.y * v.y + v.z * v.z + v.w * v.w;
        }
#pragma unroll
        for (int o = 16; o > 0; o >>= 1) {
            s  += __shfl_xor_sync(0xFFFFFFFFu, s,  o);
            sq += __shfl_xor_sync(0xFFFFFFFFu, sq, o);
        }
        if (lane == 0) {
            float mu  = s * (1.f / DIM);
            float var = sq * (1.f / DIM) - mu * mu;
            s_mu[r] = mu;
            s_rs[r] = rsqrtf(var + LN_EPS);
        }
    }
    __syncthreads();

    // warp tiling: 2(m) x 4(n); warp tile 32m x 32n
    const int wm0 = (wid & 1) * 32;
    const int wn0 = (wid >> 1) * 32;
    const int a_r  = wm0 + (lane & 15);
    const int a_cb = lane >> 4;
    const int b_n  = wn0 + (lane & 7) + ((lane & 16) >> 1);
    const int b_cb = (lane >> 3) & 1;

    float acc[2][4][4];
#pragma unroll
    for (int mt = 0; mt < 2; ++mt)
#pragma unroll
        for (int n8 = 0; n8 < 4; ++n8)
#pragma unroll
            for (int v = 0; v < 4; ++v) acc[mt][n8][v] = 0.f;

    for (int c = 0; c < 4; ++c) {
        const int s = c & 1;
        // --- stage A (normalized x, 64 rows): compute, overlaps W arrival ---
#pragma unroll
        for (int i = 0; i < 4; ++i) {
            int idx = tid + 256 * i;
            int r = idx >> 4, ch = idx & 15;
            float mu = s_mu[r], rs = s_rs[r];
            const float* xp = x + (size_t)(row0 + r) * DIM + c * 128 + ch * 8;
            const float* wl = lnw + c * 128 + ch * 8;
            const float* bl = lnb + c * 128 + ch * 8;
            __nv_bfloat16 h8[8], l8[8];
#pragma unroll
            for (int j = 0; j < 8; ++j) {
                float v = (xp[j] - mu) * rs * wl[j] + bl[j];
                h8[j] = __float2bfloat16(v);
                l8[j] = __float2bfloat16(v - __bfloat162float(h8[j]));
            }
            *(uint4*)(sm + QSA_HI + swoff(r, ch)) = *(uint4*)h8;
            *(uint4*)(sm + QSA_LO + swoff(r, ch)) = *(uint4*)l8;
        }
        asm volatile("cp.async.wait_group 1;" ::: "memory");
        __syncthreads();

#pragma unroll
        for (int ks = 0; ks < 8; ++ks) {
            uint32_t ah[2][4], al[2][4];
#pragma unroll
            for (int mt = 0; mt < 2; ++mt) {
                int r = a_r + mt * 16;
                ldsm4(sb + QSA_HI + swoff(r, ks * 2 + a_cb), ah[mt][0], ah[mt][1], ah[mt][2], ah[mt][3]);
                ldsm4(sb + QSA_LO + swoff(r, ks * 2 + a_cb), al[mt][0], al[mt][1], al[mt][2], al[mt][3]);
            }
            uint32_t bh[2][4], bl[2][4];
#pragma unroll
            for (int nb = 0; nb < 2; ++nb) {
                int n = b_n + nb * 16;
                ldsm4(sb + QSW0 + s * 65536 + swoff(n, ks * 2 + b_cb),
                      bh[nb][0], bh[nb][1], bh[nb][2], bh[nb][3]);
                ldsm4(sb + QSW0 + s * 65536 + 32768 + swoff(n, ks * 2 + b_cb),
                      bl[nb][0], bl[nb][1], bl[nb][2], bl[nb][3]);
            }
#pragma unroll
            for (int mt = 0; mt < 2; ++mt)
#pragma unroll
                for (int n8 = 0; n8 < 4; ++n8) {
                    const int nb = n8 >> 1, hf = (n8 & 1) * 2;
                    mma16816(acc[mt][n8], ah[mt], bh[nb][hf], bh[nb][hf + 1]);
                    mma16816(acc[mt][n8], ah[mt], bl[nb][hf], bl[nb][hf + 1]);
                    mma16816(acc[mt][n8], al[mt], bh[nb][hf], bh[nb][hf + 1]);
                }
        }
        __syncthreads();   // all warps done with stage s and A tile

        if (c + 2 < 4) {   // refill stage s with W chunk c+2
#pragma unroll
            for (int i = 0; i < 8; ++i) {
                int idx = tid + 256 * i;
                int r = idx >> 4, ch = idx & 15;
                cpasync16(sb + QSW0 + s * 65536 + swoff(r, ch),
                          g_wh + (size_t)r * DIM + (c + 2) * 128 + ch * 8);
                cpasync16(sb + QSW0 + s * 65536 + 32768 + swoff(r, ch),
                          g_wl + (size_t)r * DIM + (c + 2) * 128 + ch * 8);
            }
        }
        asm volatile("cp.async.commit_group;" ::: "memory");
    }

    // --- epilogue: bias + SiLU + OffsetScale -> bf16 hi/lo stores ---
#pragma unroll
    for (int n8 = 0; n8 < 4; ++n8) {
        int e0 = wn0 + n8 * 8 + (lane & 3) * 2;
        float bb0 = bq[e0],            bb1 = bq[e0 + 1];
        float g00 = gamma[e0],         g01 = gamma[e0 + 1];
        float b00 = beta[e0],          b01 = beta[e0 + 1];
        float g10 = gamma[QK + e0],    g11 = gamma[QK + e0 + 1];
        float b10 = beta[QK + e0],     b11 = beta[QK + e0 + 1];
#pragma unroll
        for (int mt = 0; mt < 2; ++mt) {
#pragma unroll
            for (int half = 0; half < 2; ++half) {
                int row = row0 + wm0 + mt * 16 + (lane >> 2) + half * 8;
                float z0 = acc[mt][n8][half * 2]     + bb0;
                float z1 = acc[mt][n8][half * 2 + 1] + bb1;
                float v0 = z0 / (1.f + expf(-z0));
                float v1 = z1 / (1.f + expf(-z1));
                float q0 = v0 * g00 + b00, q1 = v1 * g01 + b01;
                float k0 = v0 * g10 + b10, k1 = v1 * g11 + b11;
                __nv_bfloat16 t0, t1;
                size_t off = (size_t)row * QK + e0;
                t0 = __float2bfloat16(q0); t1 = __float2bfloat16(q1);
                *(uint32_t*)(g_qh + off) = (uint32_t)__bfloat16_as_ushort(t0) |
                                           ((uint32_t)__bfloat16_as_ushort(t1) << 16);
                __nv_bfloat16 r0 = __float2bfloat16(q0 - __bfloat162float(t0));
                __nv_bfloat16 r1 = __float2bfloat16(q1 - __bfloat162float(t1));
                *(uint32_t*)(g_ql + off) = (uint32_t)__bfloat16_as_ushort(r0) |
                                           ((uint32_t)__bfloat16_as_ushort(r1) << 16);
                t0 = __float2bfloat16(k0); t1 = __float2bfloat16(k1);
                *(uint32_t*)(g_kh + off) = (uint32_t)__bfloat16_as_ushort(t0) |
                                           ((uint32_t)__bfloat16_as_ushort(t1) << 16);
                r0 = __float2bfloat16(k0 - __bfloat162float(t0));
                r1 = __float2bfloat16(k1 - __bfloat162float(t1));
                *(uint32_t*)(g_kl + off) = (uint32_t)__bfloat16_as_ushort(r0) |
                                           ((uint32_t)__bfloat16_as_ushort(r1) << 16);
            }
        }
    }
}

// ---------------------------------------------------------------------------
// Kernel 2: strip-persistent HMMA sim GEMM, now 512 threads (16 warps).
// Warp grid 4(m) x 4(n), warp tile 32m x 32n.
// ---------------------------------------------------------------------------
#define SA_HI 0
#define SA_LO 32768
#define SB0   65536
#define ATT_SMEM 196608

__device__ __forceinline__ void load_tile128_512(uint32_t dst, const __nv_bfloat16* g, int tid) {
#pragma unroll
    for (int i = 0; i < 4; ++i) {
        int idx = tid + 512 * i;
        int r = idx >> 4, ch = idx & 15;
        cpasync16(dst + swoff(r, ch), g + (size_t)r * QK + ch * 8);
    }
}

__global__ __launch_bounds__(512, 1) void attn_kernel(float* __restrict__ out)
{
    extern __shared__ char smem[];
    const uint32_t sb = smem_u32(smem);
    const int tid = threadIdx.x, wid = tid >> 5, lane = tid & 31;
    const int b = blockIdx.y, strip = blockIdx.x;
    const size_t brow = (size_t)b * SEQ + strip * 128;

    const __nv_bfloat16* qh = g_qh + brow * QK;
    const __nv_bfloat16* ql = g_ql + brow * QK;
    const __nv_bfloat16* khb = g_kh + (size_t)b * SEQ * QK;
    const __nv_bfloat16* klb = g_kl + (size_t)b * SEQ * QK;

    load_tile128_512(sb + SA_HI, qh, tid);
    load_tile128_512(sb + SA_LO, ql, tid);
    load_tile128_512(sb + SB0,         khb, tid);
    load_tile128_512(sb + SB0 + 32768, klb, tid);
    asm volatile("cp.async.commit_group;" ::: "memory");
    load_tile128_512(sb + SB0 + 65536,         khb + (size_t)128 * QK, tid);
    load_tile128_512(sb + SB0 + 65536 + 32768, klb + (size_t)128 * QK, tid);
    asm volatile("cp.async.commit_group;" ::: "memory");

    // 16 warps: 4(m) x 4(n); warp tile 32m x 32n
    const int wm0 = (wid & 3) * 32;
    const int wn0 = (wid >> 2) * 32;
    const int a_r  = wm0 + (lane & 15);
    const int a_cb = lane >> 4;
    const int b_n  = wn0 + (lane & 7) + ((lane & 16) >> 1);
    const int b_cb = (lane >> 3) & 1;

    for (int jt = 0; jt < NJT; ++jt) {
        const int s = jt & 1;
        asm volatile("cp.async.wait_group 1;" ::: "memory");
        __syncthreads();

        const uint32_t sBh = sb + SB0 + s * 65536;
        const uint32_t sBl = sBh + 32768;

        float acc[2][4][4];
#pragma unroll
        for (int mt = 0; mt < 2; ++mt)
#pragma unroll
            for (int n8 = 0; n8 < 4; ++n8)
#pragma unroll
                for (int v = 0; v < 4; ++v) acc[mt][n8][v] = 0.f;

#pragma unroll
        for (int ks = 0; ks < 8; ++ks) {
            uint32_t ah[2][4], al[2][4];
#pragma unroll
            for (int mt = 0; mt < 2; ++mt) {
                int r = a_r + mt * 16;
                ldsm4(sb + SA_HI + swoff(r, ks * 2 + a_cb), ah[mt][0], ah[mt][1], ah[mt][2], ah[mt][3]);
                ldsm4(sb + SA_LO + swoff(r, ks * 2 + a_cb), al[mt][0], al[mt][1], al[mt][2], al[mt][3]);
            }
            uint32_t bh[2][4], bl[2][4];
#pragma unroll
            for (int nb = 0; nb < 2; ++nb) {
                int n = b_n + nb * 16;
                ldsm4(sBh + swoff(n, ks * 2 + b_cb), bh[nb][0], bh[nb][1], bh[nb][2], bh[nb][3]);
                ldsm4(sBl + swoff(n, ks * 2 + b_cb), bl[nb][0], bl[nb][1], bl[nb][2], bl[nb][3]);
            }
#pragma unroll
            for (int mt = 0; mt < 2; ++mt)
#pragma unroll
                for (int n8 = 0; n8 < 4; ++n8) {
                    const int nb = n8 >> 1, hf = (n8 & 1) * 2;
                    mma16816(acc[mt][n8], ah[mt], bh[nb][hf], bh[nb][hf + 1]);
                    mma16816(acc[mt][n8], ah[mt], bl[nb][hf], bl[nb][hf + 1]);
                    mma16816(acc[mt][n8], al[mt], bh[nb][hf], bh[nb][hf + 1]);
                }
        }
        __syncthreads();

        if (jt + 2 < NJT) {
            load_tile128_512(sBh, khb + (size_t)(jt + 2) * 128 * QK, tid);
            load_tile128_512(sBl, klb + (size_t)(jt + 2) * 128 * QK, tid);
        }
        asm volatile("cp.async.commit_group;" ::: "memory");

        // epilogue: relu(sim/64)^2, unnormalized
#pragma unroll
        for (int mt = 0; mt < 2; ++mt) {
#pragma unroll
            for (int n8 = 0; n8 < 4; ++n8) {
                int grow = wm0 + mt * 16 + (lane >> 2);
                int gcol = jt * 128 + wn0 + n8 * 8 + (lane & 3) * 2;
                float* p0 = out + (brow + grow) * SEQ + gcol;
                float* p1 = p0 + (size_t)8 * SEQ;
                float s0, s1;
                float2 v0, v1;
                s0 = fmaxf(acc[mt][n8][0] * 0.015625f, 0.f); v0.x = s0 * s0;
                s1 = fmaxf(acc[mt][n8][1] * 0.015625f, 0.f); v0.y = s1 * s1;
                s0 = fmaxf(acc[mt][n8][2] * 0.015625f, 0.f); v1.x = s0 * s0;
                s1 = fmaxf(acc[mt][n8][3] * 0.015625f, 0.f); v1.y = s1 * s1;
                *(float2*)p0 = v0;
                *(float2*)p1 = v1;
            }
        }
    }
}

// ---------------------------------------------------------------------------
// Kernel 3: per-row sum + in-place rescale.
// ---------------------------------------------------------------------------
__global__ __launch_bounds__(256) void norm_kernel(float* __restrict__ out)
{
    const size_t row = blockIdx.x;
    float4* p = (float4*)(out + row * SEQ);
    const int tid = threadIdx.x;

    float4 v[4];
    float s = 0.f;
#pragma unroll
    for (int i = 0; i < 4; ++i) {
        v[i] = p[tid + 256 * i];
        s += v[i].x + v[i].y + v[i].z + v[i].w;
    }

    __shared__ float red[256];
    red[tid] = s;
    __syncthreads();
#pragma unroll
    for (int o = 128; o > 0; o >>= 1) {
        if (tid < o) red[tid] += red[tid + o];
        __syncthreads();
    }
    float inv = 1.f / (red[0] + 1e-6f);

#pragma unroll
    for (int i = 0; i < 4; ++i) {
        v[i].x *= inv; v[i].y *= inv; v[i].z *= inv; v[i].w *= inv;
        p[tid + 256 * i] = v[i];
    }
}

// ---------------------------------------------------------------------------
extern "C" void kernel_launch(void* const* d_in, const int* in_sizes, int n_in,
                              void* d_out, int out_size)
{
    const float* x     = (const float*)d_in[0];
    const float* ln_w  = (const float*)d_in[1];
    const float* ln_b  = (const float*)d_in[2];
    const float* w_qk  = (const float*)d_in[3];
    const float* b_qk  = (const float*)d_in[4];
    const float* gamma = (const float*)d_in[5];
    const float* beta  = (const float*)d_in[6];
    float* out = (float*)d_out;

    wsplit_kernel<<<(QK * DIM) / (256 * 8), 256>>>(w_qk);

    cudaFuncSetAttribute(qk_kernel, cudaFuncAttributeMaxDynamicSharedMemorySize, QK_SMEM);
    qk_kernel<<<(BATCH * SEQ) / 64, 256, QK_SMEM>>>(x, ln_w, ln_b, b_qk, gamma, beta);

    cudaFuncSetAttribute(attn_kernel, cudaFuncAttributeMaxDynamicSharedMemorySize, ATT_SMEM);
    dim3 g2(SEQ / 128, BATCH);
    attn_kernel<<<g2, 512, ATT_SMEM>>>(out);

    norm_kernel<<<BATCH * SEQ, 256>>>(out);
}